// round 7
// baseline (speedup 1.0000x reference)
#include <cuda_runtime.h>

// CustomMetaPath2Vec: loss = mean(-log(sigmoid(pos_dots)+eps)) + mean(-log(1-sigmoid(neg_dots)+eps))
// pos_dots: for each of 200k rows of 7 indices: dot(emb[i0], emb[ic]) for c=1..6
// neg_dots: same over 1M rows.
// HBM-gather bound: ~4.3 GB of random 512B row gathers from a 512MB table.
//
// NUMERICS (critical): the reference computes sigmoid in fp32 and then
// 1.0 - s with cancellation; s saturates to exactly 1.0f for x > ~17.33,
// making the neg term clamp to -log(1e-15) = 34.5388. We must reproduce
// that exact fp32 behavior (accurate expf, true division, then 1-s),
// NOT the mathematically-equivalent -log(sigmoid(-x)).

#define DIM   128
#define CTX   7
#define NCTX  6          // contexts per row (CTX-1)
#define EPSF  1e-15f

__device__ double g_sums[2];   // [0]=pos sum, [1]=neg sum

__global__ void mp2v_zero_kernel() {
    g_sums[0] = 0.0;
    g_sums[1] = 0.0;
}

// fp32 sigmoid exactly as XLA's logistic expansion: 1/(1+exp(-x)).
// Inherently stable: x<<0 -> exp(-x)=inf -> s=0; x>>0 -> exp(-x)=0 -> s=1.
// Accurate expf (NOT __expf): in the cancellation region 1-s is a few ulps
// of 1.0 and fast-math error there is a ~30% relative perturbation.
__device__ __forceinline__ float sigmoid_ref(float x) {
    return 1.0f / (1.0f + expf(-x));
}

__global__ __launch_bounds__(256) void mp2v_main_kernel(
    const float* __restrict__ emb,
    const int*   __restrict__ pos_rw,
    const int*   __restrict__ neg_rw,
    int pos_rows, int neg_rows)
{
    const int lane   = threadIdx.x & 31;
    const int wib    = threadIdx.x >> 5;          // warp in block
    const int wpb    = blockDim.x >> 5;           // warps per block
    const long long total_rows = (long long)pos_rows + neg_rows;
    long long warp_g            = (long long)blockIdx.x * wpb + wib;
    const long long warp_stride = (long long)gridDim.x * wpb;

    double acc_pos = 0.0, acc_neg = 0.0;

    for (long long row = warp_g; row < total_rows; row += warp_stride) {
        const bool is_pos = (row < (long long)pos_rows);
        const int* rw = is_pos ? (pos_rw + row * CTX)
                               : (neg_rw + (row - pos_rows) * CTX);

        // 7 indices: lanes 0..6 load one each, broadcast via shfl.
        int my_idx = (lane < CTX) ? rw[lane] : 0;

        // Issue ALL 7 row gathers back-to-back (one LDG.128 per lane each)
        // before any compute -> MLP = 7 per warp.
        int i0 = __shfl_sync(0xffffffffu, my_idx, 0);
        float4 h = ((const float4*)(emb + (long long)i0 * DIM))[lane];

        float4 c[NCTX];
        #pragma unroll
        for (int j = 0; j < NCTX; j++) {
            int ij = __shfl_sync(0xffffffffu, my_idx, j + 1);
            c[j] = ((const float4*)(emb + (long long)ij * DIM))[lane];
        }

        // Per-lane partial dots (4 elems each), 6 independent chains.
        float p[NCTX];
        #pragma unroll
        for (int j = 0; j < NCTX; j++) {
            float d;
            d = h.x * c[j].x;
            d = fmaf(h.y, c[j].y, d);
            d = fmaf(h.z, c[j].z, d);
            d = fmaf(h.w, c[j].w, d);
            p[j] = d;
        }

        // Butterfly warp reduction, 6 chains in parallel (ILP over SHFL lat).
        #pragma unroll
        for (int off = 16; off > 0; off >>= 1) {
            #pragma unroll
            for (int j = 0; j < NCTX; j++)
                p[j] += __shfl_xor_sync(0xffffffffu, p[j], off);
        }

        if (lane == 0) {
            float local = 0.0f;
            if (is_pos) {
                #pragma unroll
                for (int j = 0; j < NCTX; j++) {
                    float s = sigmoid_ref(p[j]);
                    local += -logf(s + EPSF);
                }
                acc_pos += (double)local;
            } else {
                #pragma unroll
                for (int j = 0; j < NCTX; j++) {
                    float s = sigmoid_ref(p[j]);
                    // fp32 cancellation + clamp, exactly like the reference:
                    // for p[j] > ~17.33, s == 1.0f -> term = -log(1e-15).
                    local += -logf(1.0f - s + EPSF);
                }
                acc_neg += (double)local;
            }
        }
    }

    // Block-level reduction -> 2 atomics per CTA (grid ~1184 CTAs -> ~2.4k atomics).
    __shared__ double s_pos[8], s_neg[8];
    if (lane == 0) { s_pos[wib] = acc_pos; s_neg[wib] = acc_neg; }
    __syncthreads();
    if (threadIdx.x == 0) {
        double sp = 0.0, sn = 0.0;
        for (int w = 0; w < wpb; w++) { sp += s_pos[w]; sn += s_neg[w]; }
        if (sp != 0.0) atomicAdd(&g_sums[0], sp);
        if (sn != 0.0) atomicAdd(&g_sums[1], sn);
    }
}

__global__ void mp2v_finalize_kernel(float* out, long long n_pos_terms, long long n_neg_terms) {
    out[0] = (float)(g_sums[0] / (double)n_pos_terms +
                     g_sums[1] / (double)n_neg_terms);
}

extern "C" void kernel_launch(void* const* d_in, const int* in_sizes, int n_in,
                              void* d_out, int out_size) {
    const float* emb    = (const float*)d_in[0];
    const int*   pos_rw = (const int*)d_in[1];
    const int*   neg_rw = (const int*)d_in[2];
    float*       out    = (float*)d_out;

    const int pos_rows = in_sizes[1] / CTX;   // 200000
    const int neg_rows = in_sizes[2] / CTX;   // 1000000

    mp2v_zero_kernel<<<1, 1>>>();

    // Fill the chip: 148 SMs x 8 CTAs (2048 thr/SM), persistent grid-stride.
    const int threads = 256;
    const int blocks  = 148 * 8;
    mp2v_main_kernel<<<blocks, threads>>>(emb, pos_rw, neg_rw, pos_rows, neg_rows);

    mp2v_finalize_kernel<<<1, 1>>>(out,
                                   (long long)pos_rows * NCTX,
                                   (long long)neg_rows * NCTX);
}

// round 8
// speedup vs baseline: 1.9030x; 1.9030x over previous
#include <cuda_runtime.h>

// CustomMetaPath2Vec: loss = mean(-log(sigmoid(pos_dots)+eps)) + mean(-log(1-sigmoid(neg_dots)+eps))
// 1.2M rows x 7 random gathers of 512B embedding rows = 4.3 GB gather-bound.
//
// R7 changes vs 1021us version (latency-chain bound, not BW bound):
//  - 4 rows per warp iteration, ONE coalesced 28-lane index load (amortize idx latency,
//    make rows 1-3 addresses register-resident so gathers overlap prior-row compute)
//  - post-butterfly, lane j computes term j (6-way parallel transcendentals instead of
//    lane-0 serializing 6x exp/div/log); per-lane float accumulators
//  - __ldcg on embedding gathers (L1 hit prob ~0.04%: don't allocate)
//  - per-CTA partial slots instead of zero-kernel+atomicAdd (2 launches, overwrite-determinism)
//
// NUMERICS (do not touch): s = 1.0f/(1.0f+expf(-x)); pos: -logf(s+1e-15f);
// neg: -logf(1.0f-s+1e-15f). Exact fp32 cancellation/saturation match -> rel_err 0.0.

#define DIM      128
#define CTX      7
#define NCTX     6
#define EPSF     1e-15f
#define NTHREADS 256
#define NBLOCKS  (148 * 8)
#define GROUP    4          // rows per warp iteration (GROUP*CTX = 28 <= 32 lanes)

__device__ double g_part_pos[NBLOCKS];
__device__ double g_part_neg[NBLOCKS];

__global__ __launch_bounds__(NTHREADS) void mp2v_main_kernel(
    const float* __restrict__ emb,
    const int*   __restrict__ pos_rw,
    const int*   __restrict__ neg_rw,
    int pos_rows, int neg_rows)
{
    const int lane = threadIdx.x & 31;
    const int wib  = threadIdx.x >> 5;
    const int wpb  = NTHREADS >> 5;

    const long long total   = (long long)pos_rows + neg_rows;
    const long long ngroups = (total + GROUP - 1) / GROUP;
    long long gidx          = (long long)blockIdx.x * wpb + wib;
    const long long gstride = (long long)gridDim.x * wpb;

    // Per-lane accumulators (lanes 0..5 active). Each lane sums <= ~260 terms
    // of magnitude <= 34.54 in fp32 -> ~1e-6 relative error, promoted to
    // double at warp reduce.
    float accp = 0.0f, accn = 0.0f;

    for (; gidx < ngroups; gidx += gstride) {
        const long long r0 = gidx * GROUP;
        const int nrows = (int)((total - r0 < GROUP) ? (total - r0) : GROUP);

        // One coalesced 28-lane index load serves all 4 rows of this group.
        // (pos/neg boundary at 200000 is GROUP-aligned, but keep a generic
        // straddle fallback for safety.)
        const bool grp_in_pos = (r0 < (long long)pos_rows);
        const bool straddle   = grp_in_pos && (r0 + nrows > (long long)pos_rows);
        int myidx = 0;
        if (!straddle) {
            const int* base = grp_in_pos ? (pos_rw + r0 * CTX)
                                         : (neg_rw + (r0 - pos_rows) * CTX);
            if (lane < nrows * CTX) myidx = base[lane];
        } else {
            if (lane < nrows * CTX) {
                const int r  = lane / CTX, c2 = lane % CTX;
                const long long rr = r0 + r;
                myidx = (rr < (long long)pos_rows)
                          ? pos_rw[rr * CTX + c2]
                          : neg_rw[(rr - pos_rows) * CTX + c2];
            }
        }

        #pragma unroll
        for (int r = 0; r < GROUP; r++) {
            if (r >= nrows) break;
            const bool is_pos = (r0 + r) < (long long)pos_rows;

            // Addresses come from register shfl only -> gathers of this row
            // can issue while the previous row's butterfly/compute drains.
            const int i0 = __shfl_sync(0xffffffffu, myidx, r * CTX);
            float4 h = __ldcg((const float4*)(emb + (long long)i0 * DIM) + lane);

            float4 cv[NCTX];
            #pragma unroll
            for (int j = 0; j < NCTX; j++) {
                const int ij = __shfl_sync(0xffffffffu, myidx, r * CTX + j + 1);
                cv[j] = __ldcg((const float4*)(emb + (long long)ij * DIM) + lane);
            }

            float p[NCTX];
            #pragma unroll
            for (int j = 0; j < NCTX; j++) {
                float d = h.x * cv[j].x;
                d = fmaf(h.y, cv[j].y, d);
                d = fmaf(h.z, cv[j].z, d);
                d = fmaf(h.w, cv[j].w, d);
                p[j] = d;
            }

            // Butterfly reduce, 6 independent chains (ILP over SHFL latency).
            #pragma unroll
            for (int off = 16; off > 0; off >>= 1) {
                #pragma unroll
                for (int j = 0; j < NCTX; j++)
                    p[j] += __shfl_xor_sync(0xffffffffu, p[j], off);
            }

            // Lane j takes dot j (static selects, no dynamic-index spill);
            // 6-way parallel exp/div/log instead of lane-0 doing all 6.
            float x = p[0];
            #pragma unroll
            for (int j = 1; j < NCTX; j++)
                if (lane == j) x = p[j];

            if (lane < NCTX) {
                const float s = 1.0f / (1.0f + expf(-x));
                if (is_pos) accp += -logf(s + EPSF);
                else        accn += -logf(1.0f - s + EPSF);
            }
        }
    }

    // Warp reduce in double, then block reduce, then per-CTA partial slot
    // (overwritten every call: no zeroing, no atomics, deterministic).
    double dp = (double)accp, dn = (double)accn;
    #pragma unroll
    for (int off = 16; off > 0; off >>= 1) {
        dp += __shfl_xor_sync(0xffffffffu, dp, off);
        dn += __shfl_xor_sync(0xffffffffu, dn, off);
    }

    __shared__ double s_pos[NTHREADS >> 5], s_neg[NTHREADS >> 5];
    if (lane == 0) { s_pos[wib] = dp; s_neg[wib] = dn; }
    __syncthreads();
    if (threadIdx.x == 0) {
        double sp = 0.0, sn = 0.0;
        #pragma unroll
        for (int w = 0; w < (NTHREADS >> 5); w++) { sp += s_pos[w]; sn += s_neg[w]; }
        g_part_pos[blockIdx.x] = sp;
        g_part_neg[blockIdx.x] = sn;
    }
}

__global__ __launch_bounds__(256) void mp2v_finalize_kernel(
    float* out, long long n_pos_terms, long long n_neg_terms)
{
    __shared__ double sp[256], sn[256];
    double a = 0.0, b = 0.0;
    for (int i = threadIdx.x; i < NBLOCKS; i += 256) {
        a += g_part_pos[i];
        b += g_part_neg[i];
    }
    sp[threadIdx.x] = a; sn[threadIdx.x] = b;
    __syncthreads();
    for (int s = 128; s > 0; s >>= 1) {
        if (threadIdx.x < s) {
            sp[threadIdx.x] += sp[threadIdx.x + s];
            sn[threadIdx.x] += sn[threadIdx.x + s];
        }
        __syncthreads();
    }
    if (threadIdx.x == 0)
        out[0] = (float)(sp[0] / (double)n_pos_terms + sn[0] / (double)n_neg_terms);
}

extern "C" void kernel_launch(void* const* d_in, const int* in_sizes, int n_in,
                              void* d_out, int out_size) {
    const float* emb    = (const float*)d_in[0];
    const int*   pos_rw = (const int*)d_in[1];
    const int*   neg_rw = (const int*)d_in[2];
    float*       out    = (float*)d_out;

    const int pos_rows = in_sizes[1] / CTX;   // 200000
    const int neg_rows = in_sizes[2] / CTX;   // 1000000

    mp2v_main_kernel<<<NBLOCKS, NTHREADS>>>(emb, pos_rw, neg_rw, pos_rows, neg_rows);
    mp2v_finalize_kernel<<<1, 256>>>(out,
                                     (long long)pos_rows * NCTX,
                                     (long long)neg_rows * NCTX);
}